// round 9
// baseline (speedup 1.0000x reference)
#include <cuda_runtime.h>
#include <cuda_bf16.h>

#define BATCH 8192
#define DIM   16
#define DIM1  48
#define TTH   20
#define VOCAB 32000

// Scratch (no runtime allocation allowed)
__device__ float g_o[BATCH * DIM];          // stage-1 output o[b][k]
__device__ float g_et[DIM * VOCAB];         // transposed embed: g_et[k][v]

// ---------------------------------------------------------------------------
// packed f32x2 helpers
// ---------------------------------------------------------------------------
__device__ __forceinline__ unsigned long long f2fma(unsigned long long a,
                                                    unsigned long long b,
                                                    unsigned long long c) {
    unsigned long long d;
    asm("fma.rn.f32x2 %0, %1, %2, %3;" : "=l"(d) : "l"(a), "l"(b), "l"(c));
    return d;
}
__device__ __forceinline__ unsigned long long fdup(float x) {
    unsigned long long d;
    asm("mov.b64 %0, {%1, %1};" : "=l"(d) : "f"(x));
    return d;
}
__device__ __forceinline__ void cp_async16(void* smem_dst, const void* gmem_src) {
    unsigned d = (unsigned)__cvta_generic_to_shared(smem_dst);
    asm volatile("cp.async.cg.shared.global [%0], [%1], 16;\n"
                 :: "r"(d), "l"(gmem_src) : "memory");
}
__device__ __forceinline__ void cp_async_wait_all() {
    asm volatile("cp.async.commit_group;\n" ::: "memory");
    asm volatile("cp.async.wait_group 0;\n" ::: "memory");
}

// ---------------------------------------------------------------------------
// Kernel 0: transpose embed_w [VOCAB,16] -> g_et[16][VOCAB]
// One thread per vocab row: coalesced float4 reads; for fixed k, consecutive
// threads write consecutive g_et addresses -> coalesced 128B stores.
// ---------------------------------------------------------------------------
__global__ __launch_bounds__(256) void k_transpose(const float* __restrict__ E) {
    int e = blockIdx.x * 256 + threadIdx.x;
    if (e >= VOCAB) return;
    const float4* r = (const float4*)(E + (size_t)e * DIM);
#pragma unroll
    for (int q = 0; q < 4; q++) {
        float4 v = r[q];
        g_et[(q * 4 + 0) * VOCAB + e] = v.x;
        g_et[(q * 4 + 1) * VOCAB + e] = v.y;
        g_et[(q * 4 + 2) * VOCAB + e] = v.z;
        g_et[(q * 4 + 3) * VOCAB + e] = v.w;
    }
}

// ---------------------------------------------------------------------------
// Stage 1: warp-per-row MLP. 512 threads (16 warps = 16 rows) per block.
// Weights transposed (i-major) in dynamic smem with ODD row strides (49/17):
//  - preamble: source-linear coalesced LDG, conflict-free scattered STS
//  - mainloop: lane-consecutive conflict-free LDS
// ---------------------------------------------------------------------------
// smem float offsets (strides: 48-wide rows padded to 49, 16-wide to 17)
#define O_WI1 0          // [16][48] s49 -> 784
#define O_WA1 784        // [48][16] s17 -> 816
#define O_WM1 1600       // [80][48] s49 -> 3920
#define O_WM2 5520       // [112][48] s49 -> 5488
#define O_WM3 11008      // [48][48] s49 -> 2352
#define O_WO1 13360      // [48][16] s17 -> 816
#define O_B   14176      // biases: bI1@0 bA1@48 bM1@64 bM2@112 bM3@160 lng@208 lnb@256 bO1@304
#define O_WS  14496      // per-warp scratch: 16 warps * 192
#define SM_FLOATS 17568  // 70272 bytes

__device__ __forceinline__ float wredsum(float v) {
#pragma unroll
    for (int o = 16; o; o >>= 1) v += __shfl_xor_sync(0xffffffffu, v, o);
    return v;
}

// LayerNorm(48) + SiLU: hA on all 32 lanes (j=lane), hB on lanes<16 (j=32+lane).
__device__ __forceinline__ void ln_silu_warp(float& hA, float& hB, int lane,
                                             const float* g, const float* bt) {
    float s = hA + (lane < 16 ? hB : 0.f);
    s = wredsum(s);
    float mu = s * (1.0f / DIM1);
    float dA = hA - mu, dB = hB - mu;
    float v = dA * dA + (lane < 16 ? dB * dB : 0.f);
    v = wredsum(v);
    float r = rsqrtf(v * (1.0f / DIM1) + 1e-5f);
    float yA = dA * r * g[lane] + bt[lane];
    hA = yA / (1.0f + __expf(-yA));
    if (lane < 16) {
        float yB = dB * r * g[32 + lane] + bt[32 + lane];
        hB = yB / (1.0f + __expf(-yB));
    }
}

__global__ __launch_bounds__(512) void k_stage1(
    const float* __restrict__ we,  const float* __restrict__ ctx,
    const float* __restrict__ th,
    const float* __restrict__ WI1, const float* __restrict__ bI1,
    const float* __restrict__ WA1, const float* __restrict__ bA1,
    const float* __restrict__ WM1, const float* __restrict__ bM1,
    const float* __restrict__ WM2, const float* __restrict__ bM2,
    const float* __restrict__ WM3, const float* __restrict__ bM3,
    const float* __restrict__ lng, const float* __restrict__ lnb,
    const float* __restrict__ WO1, const float* __restrict__ bO1)
{
    extern __shared__ float sm[];
    const int tid = threadIdx.x;

    // ---- load weights: coalesced source-linear reads, scattered STS ----
    for (int idx = tid; idx < 768; idx += 512) {        // WI1 [48][16] -> [i=16][j=48] s49
        int j = idx / 16, i = idx % 16;
        sm[O_WI1 + i * 49 + j] = WI1[idx];
    }
    for (int idx = tid; idx < 768; idx += 512) {        // WA1 [16][48] -> [i=48][j=16] s17
        int j = idx / 48, i = idx % 48;
        sm[O_WA1 + i * 17 + j] = WA1[idx];
    }
    for (int idx = tid; idx < 3840; idx += 512) {       // WM1 [48][80] -> [i=80][j=48] s49
        int j = idx / 80, i = idx % 80;
        sm[O_WM1 + i * 49 + j] = WM1[idx];
    }
    for (int idx = tid; idx < 5376; idx += 512) {       // WM2 [48][112] -> [i=112][j=48] s49
        int j = idx / 112, i = idx % 112;
        sm[O_WM2 + i * 49 + j] = WM2[idx];
    }
    for (int idx = tid; idx < 2304; idx += 512) {       // WM3 [48][48] -> [i][j] s49
        int j = idx / 48, i = idx % 48;
        sm[O_WM3 + i * 49 + j] = WM3[idx];
    }
    for (int idx = tid; idx < 768; idx += 512) {        // WO1 [16][48] -> [i=48][j=16] s17
        int j = idx / 48, i = idx % 48;
        sm[O_WO1 + i * 17 + j] = WO1[idx];
    }
    if (tid < 48)  sm[O_B + tid]        = bI1[tid];
    if (tid < 16)  sm[O_B + 48 + tid]   = bA1[tid];
    if (tid < 48)  sm[O_B + 64 + tid]   = bM1[tid];
    if (tid < 48)  sm[O_B + 112 + tid]  = bM2[tid];
    if (tid < 48)  sm[O_B + 160 + tid]  = bM3[tid];
    if (tid < 48)  sm[O_B + 208 + tid]  = lng[tid];
    if (tid < 48)  sm[O_B + 256 + tid]  = lnb[tid];
    if (tid < 16)  sm[O_B + 304 + tid]  = bO1[tid];
    __syncthreads();

    const int lane = tid & 31;
    const int w    = tid >> 5;
    const int b    = blockIdx.x * 16 + w;
    float* ws = sm + O_WS + w * 192;   // out[0..47] op[48..63] h[64..111] tp/h2[112..159] sc[160..179]
    const float* sG  = sm + O_B + 208;
    const float* sBt = sm + O_B + 256;

    // row inputs (uniform per warp -> broadcast loads)
    float x[DIM], c[DIM];
    {
        const float4* xp = (const float4*)(we  + (size_t)b * DIM);
        const float4* cp = (const float4*)(ctx + (size_t)b * DIM);
#pragma unroll
        for (int q = 0; q < 4; q++) {
            float4 vx = __ldg(&xp[q]); x[q*4+0]=vx.x; x[q*4+1]=vx.y; x[q*4+2]=vx.z; x[q*4+3]=vx.w;
            float4 vc = __ldg(&cp[q]); c[q*4+0]=vc.x; c[q*4+1]=vc.y; c[q*4+2]=vc.z; c[q*4+3]=vc.w;
        }
    }

    // ---- I1: out[48] ----
    {
        float a = sm[O_B + lane];
        float a2 = (lane < 16) ? sm[O_B + 32 + lane] : 0.f;
#pragma unroll
        for (int i = 0; i < DIM; i++) {
            a += sm[O_WI1 + i * 49 + lane] * x[i];
            if (lane < 16) a2 += sm[O_WI1 + i * 49 + 32 + lane] * x[i];
        }
        ws[lane] = a;
        if (lane < 16) ws[32 + lane] = a2;
    }
    __syncwarp();

    // ---- A1: op[16] ----
    if (lane < 16) {
        float a = sm[O_B + 48 + lane];
#pragma unroll
        for (int i = 0; i < DIM1; i++) a += sm[O_WA1 + i * 17 + lane] * ws[i];
        ws[48 + lane] = a;
    }
    __syncwarp();

    // ---- M1 + LN + SiLU -> h[48] ----
    {
        float hA = sm[O_B + 64 + lane];
        float hB = (lane < 16) ? sm[O_B + 64 + 32 + lane] : 0.f;
#pragma unroll
        for (int i = 0; i < DIM1; i++) {
            float vi = ws[i];
            hA += sm[O_WM1 + i * 49 + lane] * vi;
            if (lane < 16) hB += sm[O_WM1 + i * 49 + 32 + lane] * vi;
        }
#pragma unroll
        for (int i = 0; i < DIM; i++) {
            hA += sm[O_WM1 + (48 + i) * 49 + lane] * c[i];
            if (lane < 16) hB += sm[O_WM1 + (48 + i) * 49 + 32 + lane] * c[i];
        }
#pragma unroll
        for (int i = 0; i < DIM; i++) {
            float vi = ws[48 + i];
            hA += sm[O_WM1 + (64 + i) * 49 + lane] * vi;
            if (lane < 16) hB += sm[O_WM1 + (64 + i) * 49 + 32 + lane] * vi;
        }
        ln_silu_warp(hA, hB, lane, sG, sBt);
        ws[64 + lane] = hA;
        if (lane < 16) ws[96 + lane] = hB;
    }
    __syncwarp();

    // ---- scores ----
    if (lane < TTH) {
        const float4* tr = (const float4*)(th + (size_t)b * TTH * DIM + lane * DIM);
        float s = 0.f;
#pragma unroll
        for (int q = 0; q < 4; q++) {
            float4 v = __ldg(&tr[q]);
            s += v.x * ws[48 + q*4+0] + v.y * ws[48 + q*4+1]
               + v.z * ws[48 + q*4+2] + v.w * ws[48 + q*4+3];
        }
        ws[160 + lane] = s;
    }
    __syncwarp();

    // ---- top-3 (replicated per lane; identical compare chain to reference) ----
    float s0 = -3.0e38f, s1 = -3.0e38f, s2 = -3.0e38f;
    int   i0 = 0, i1 = 0, i2 = 0;
#pragma unroll
    for (int t = 0; t < TTH; t++) {
        float s = ws[160 + t];
        if (s > s0)      { s2=s1; i2=i1; s1=s0; i1=i0; s0=s; i0=t; }
        else if (s > s1) { s2=s1; i2=i1; s1=s;  i1=t; }
        else if (s > s2) { s2=s;  i2=t; }
    }
    if (lane < 16) {
        const float* tb = th + (size_t)b * TTH * DIM;
        ws[112 + lane] = __ldg(&tb[i0 * DIM + lane]);
        ws[128 + lane] = __ldg(&tb[i1 * DIM + lane]);
        ws[144 + lane] = __ldg(&tb[i2 * DIM + lane]);
    }
    __syncwarp();

    // ---- M2 + LN + SiLU -> h2 ----
    float h2A, h2B;
    {
        float hA = sm[O_B + 112 + lane];
        float hB = (lane < 16) ? sm[O_B + 112 + 32 + lane] : 0.f;
#pragma unroll
        for (int i = 0; i < DIM1; i++) {
            float vi = ws[64 + i];
            hA += sm[O_WM2 + i * 49 + lane] * vi;
            if (lane < 16) hB += sm[O_WM2 + i * 49 + 32 + lane] * vi;
        }
#pragma unroll
        for (int i = 0; i < DIM1; i++) {
            float vi = ws[112 + i];
            hA += sm[O_WM2 + (48 + i) * 49 + lane] * vi;
            if (lane < 16) hB += sm[O_WM2 + (48 + i) * 49 + 32 + lane] * vi;
        }
#pragma unroll
        for (int i = 0; i < DIM; i++) {
            hA += sm[O_WM2 + (96 + i) * 49 + lane] * c[i];
            if (lane < 16) hB += sm[O_WM2 + (96 + i) * 49 + 32 + lane] * c[i];
        }
        ln_silu_warp(hA, hB, lane, sG, sBt);
        h2A = hA; h2B = hB;
    }
    __syncwarp();                 // everyone done reading ws[112..159] (tp)
    ws[112 + lane] = h2A;
    if (lane < 16) ws[144 + lane] = h2B;
    __syncwarp();

    // ---- M3 + LN + SiLU -> h3 ----
    float h3A, h3B;
    {
        float hA = sm[O_B + 160 + lane];
        float hB = (lane < 16) ? sm[O_B + 160 + 32 + lane] : 0.f;
#pragma unroll
        for (int i = 0; i < DIM1; i++) {
            float vi = ws[112 + i];
            hA += sm[O_WM3 + i * 49 + lane] * vi;
            if (lane < 16) hB += sm[O_WM3 + i * 49 + 32 + lane] * vi;
        }
        ln_silu_warp(hA, hB, lane, sG, sBt);
        h3A = hA; h3B = hB;
    }
    ws[lane] = h3A;               // slot 0..47 free (out no longer needed)
    if (lane < 16) ws[32 + lane] = h3B;
    __syncwarp();

    // ---- O1 -> g_o ----
    if (lane < 16) {
        float a = sm[O_B + 304 + lane];
#pragma unroll
        for (int i = 0; i < DIM1; i++) a += sm[O_WO1 + i * 17 + lane] * ws[i];
        g_o[(size_t)b * DIM + lane] = a;
    }
}

// ---------------------------------------------------------------------------
// Stage 2: logits GEMM  [8192,16] x [16,32000] -> [8192,32000]
// Block tile: 64 batch x 128 vocab, 128 threads, 4 CTAs/SM.
// Thread tile: 8 batch x 8 vocab (f32x2 packed, FFMA2).
// E tile from pre-transposed g_et via cp.async (no LDG->reg->STS transpose).
// ---------------------------------------------------------------------------
#define ES_STRIDE 132   // floats; 528 B rows (16B-aligned)

__global__ __launch_bounds__(128, 4) void k_gemm(float* __restrict__ out)
{
    __shared__ float es[DIM][ES_STRIDE];   // es[k][v]
    __shared__ float os[DIM][64];          // os[k][b]

    const int tid = threadIdx.x;
    const int v0 = blockIdx.x * 128;
    const int b0 = blockIdx.y * 64;

    // E tile: 16 rows x 128 floats via 512 cp.async.cg (16 B each), contiguous src.
#pragma unroll
    for (int q = 0; q < 4; q++) {
        int f = tid + q * 128;          // 0..511
        int k  = f >> 5;                // row 0..15
        int j4 = f & 31;                // float4 within row
        cp_async16(&es[k][j4 * 4], &g_et[(size_t)k * VOCAB + v0 + j4 * 4]);
    }
    // o tile (small): LDG + transpose STS
    if (tid < 64) {
        const float4* orow = (const float4*)&g_o[(size_t)(b0 + tid) * DIM];
#pragma unroll
        for (int q = 0; q < 4; q++) {
            float4 r = orow[q];
            os[q * 4 + 0][tid] = r.x;
            os[q * 4 + 1][tid] = r.y;
            os[q * 4 + 2][tid] = r.z;
            os[q * 4 + 3][tid] = r.w;
        }
    }
    cp_async_wait_all();
    __syncthreads();

    const int tx = tid & 15;    // vocab: cols tx*4..+3 and 64+tx*4..+3
    const int ty = tid >> 4;    // batch: rows b0 + ty*8 .. +7

    unsigned long long acc[8][4];
#pragma unroll
    for (int m = 0; m < 8; m++)
#pragma unroll
        for (int n = 0; n < 4; n++) acc[m][n] = 0ull;

#pragma unroll
    for (int k = 0; k < DIM; k++) {
        ulonglong2 eA = *(const ulonglong2*)&es[k][tx * 4];        // LDS.128
        ulonglong2 eB = *(const ulonglong2*)&es[k][64 + tx * 4];   // LDS.128
        float4 oA = *(const float4*)&os[k][ty * 8];                // LDS.128 bcast
        float4 oB = *(const float4*)&os[k][ty * 8 + 4];            // LDS.128 bcast
        unsigned long long a0 = fdup(oA.x), a1 = fdup(oA.y);
        unsigned long long a2 = fdup(oA.z), a3 = fdup(oA.w);
        unsigned long long a4 = fdup(oB.x), a5 = fdup(oB.y);
        unsigned long long a6 = fdup(oB.z), a7 = fdup(oB.w);
        unsigned long long av[8] = {a0, a1, a2, a3, a4, a5, a6, a7};
#pragma unroll
        for (int m = 0; m < 8; m++) {
            acc[m][0] = f2fma(av[m], eA.x, acc[m][0]);
            acc[m][1] = f2fma(av[m], eA.y, acc[m][1]);
            acc[m][2] = f2fma(av[m], eB.x, acc[m][2]);
            acc[m][3] = f2fma(av[m], eB.y, acc[m][3]);
        }
    }

    union U { ulonglong2 u; float4 f; };
#pragma unroll
    for (int m = 0; m < 8; m++) {
        size_t row = (size_t)(b0 + ty * 8 + m) * VOCAB + v0;
        U u1; u1.u.x = acc[m][0]; u1.u.y = acc[m][1];
        U u2; u2.u.x = acc[m][2]; u2.u.y = acc[m][3];
        __stcs((float4*)&out[row + tx * 4],      u1.f);   // streaming store
        __stcs((float4*)&out[row + 64 + tx * 4], u2.f);
    }
}

// ---------------------------------------------------------------------------
extern "C" void kernel_launch(void* const* d_in, const int* in_sizes, int n_in,
                              void* d_out, int out_size) {
    const float* we  = (const float*)d_in[0];
    const float* ctx = (const float*)d_in[1];
    const float* th  = (const float*)d_in[2];
    const float* WI1 = (const float*)d_in[3];  const float* bI1 = (const float*)d_in[4];
    const float* WA1 = (const float*)d_in[5];  const float* bA1 = (const float*)d_in[6];
    const float* WM1 = (const float*)d_in[7];  const float* bM1 = (const float*)d_in[8];
    const float* WM2 = (const float*)d_in[9];  const float* bM2 = (const float*)d_in[10];
    const float* WM3 = (const float*)d_in[11]; const float* bM3 = (const float*)d_in[12];
    const float* lng = (const float*)d_in[13]; const float* lnb = (const float*)d_in[14];
    const float* WO1 = (const float*)d_in[15]; const float* bO1 = (const float*)d_in[16];
    const float* E   = (const float*)d_in[17];
    float* out = (float*)d_out;

    // Unconditional (no static guard): deterministic, idempotent, capture-safe.
    cudaFuncSetAttribute(k_stage1, cudaFuncAttributeMaxDynamicSharedMemorySize,
                         SM_FLOATS * 4);

    k_transpose<<<(VOCAB + 255) / 256, 256>>>(E);
    k_stage1<<<BATCH / 16, 512, SM_FLOATS * 4>>>(we, ctx, th, WI1, bI1, WA1, bA1,
                                                 WM1, bM1, WM2, bM2, WM3, bM3,
                                                 lng, lnb, WO1, bO1);
    dim3 grid(VOCAB / 128, BATCH / 64);
    k_gemm<<<grid, 128>>>(out);
}

// round 11
// speedup vs baseline: 1.4890x; 1.4890x over previous
#include <cuda_runtime.h>
#include <cuda_bf16.h>

#define BATCH 8192
#define DIM   16
#define DIM1  48
#define TTH   20
#define VOCAB 32000

// Scratch (no runtime allocation allowed)
__device__ float g_o[BATCH * DIM];        // stage-1 output o[b][k]

// ---------------------------------------------------------------------------
// packed f32x2 helpers
// ---------------------------------------------------------------------------
__device__ __forceinline__ unsigned long long f2fma(unsigned long long a,
                                                    unsigned long long b,
                                                    unsigned long long c) {
    unsigned long long d;
    asm("fma.rn.f32x2 %0, %1, %2, %3;" : "=l"(d) : "l"(a), "l"(b), "l"(c));
    return d;
}
__device__ __forceinline__ unsigned long long fdup(float x) {
    unsigned long long d;
    asm("mov.b64 %0, {%1, %1};" : "=l"(d) : "f"(x));
    return d;
}

// ---------------------------------------------------------------------------
// Stage 1: warp-per-row MLP. 512 threads (16 warps = 16 rows) per block.
// Weights transposed (i-major) in dynamic smem with ODD row strides (49/17):
//  - preamble: source-linear coalesced LDG, conflict-free scattered STS
//    (odd stride => bank step coprime with 32)
//  - mainloop: lane-consecutive conflict-free LDS
// ---------------------------------------------------------------------------
// smem float offsets (strides: 48-wide rows padded to 49, 16-wide to 17)
#define O_WI1 0          // [16][48] s49 -> 784
#define O_WA1 784        // [48][16] s17 -> 816
#define O_WM1 1600       // [80][48] s49 -> 3920
#define O_WM2 5520       // [112][48] s49 -> 5488
#define O_WM3 11008      // [48][48] s49 -> 2352
#define O_WO1 13360      // [48][16] s17 -> 816
#define O_B   14176      // biases: bI1@0 bA1@48 bM1@64 bM2@112 bM3@160 lng@208 lnb@256 bO1@304
#define O_WS  14496      // per-warp scratch: 16 warps * 192
#define SM_FLOATS 17568  // 70272 bytes

__device__ __forceinline__ float wredsum(float v) {
#pragma unroll
    for (int o = 16; o; o >>= 1) v += __shfl_xor_sync(0xffffffffu, v, o);
    return v;
}

// LayerNorm(48) + SiLU: hA on all 32 lanes (j=lane), hB on lanes<16 (j=32+lane).
__device__ __forceinline__ void ln_silu_warp(float& hA, float& hB, int lane,
                                             const float* g, const float* bt) {
    float s = hA + (lane < 16 ? hB : 0.f);
    s = wredsum(s);
    float mu = s * (1.0f / DIM1);
    float dA = hA - mu, dB = hB - mu;
    float v = dA * dA + (lane < 16 ? dB * dB : 0.f);
    v = wredsum(v);
    float r = rsqrtf(v * (1.0f / DIM1) + 1e-5f);
    float yA = dA * r * g[lane] + bt[lane];
    hA = yA / (1.0f + __expf(-yA));
    if (lane < 16) {
        float yB = dB * r * g[32 + lane] + bt[32 + lane];
        hB = yB / (1.0f + __expf(-yB));
    }
}

__global__ __launch_bounds__(512) void k_stage1(
    const float* __restrict__ we,  const float* __restrict__ ctx,
    const float* __restrict__ th,
    const float* __restrict__ WI1, const float* __restrict__ bI1,
    const float* __restrict__ WA1, const float* __restrict__ bA1,
    const float* __restrict__ WM1, const float* __restrict__ bM1,
    const float* __restrict__ WM2, const float* __restrict__ bM2,
    const float* __restrict__ WM3, const float* __restrict__ bM3,
    const float* __restrict__ lng, const float* __restrict__ lnb,
    const float* __restrict__ WO1, const float* __restrict__ bO1)
{
    extern __shared__ float sm[];
    const int tid = threadIdx.x;

    // ---- load weights: coalesced source-linear reads, scattered STS ----
    for (int idx = tid; idx < 768; idx += 512) {        // WI1 [48][16] -> [i=16][j=48] s49
        int j = idx / 16, i = idx % 16;
        sm[O_WI1 + i * 49 + j] = WI1[idx];
    }
    for (int idx = tid; idx < 768; idx += 512) {        // WA1 [16][48] -> [i=48][j=16] s17
        int j = idx / 48, i = idx % 48;
        sm[O_WA1 + i * 17 + j] = WA1[idx];
    }
    for (int idx = tid; idx < 3840; idx += 512) {       // WM1 [48][80] -> [i=80][j=48] s49
        int j = idx / 80, i = idx % 80;
        sm[O_WM1 + i * 49 + j] = WM1[idx];
    }
    for (int idx = tid; idx < 5376; idx += 512) {       // WM2 [48][112] -> [i=112][j=48] s49
        int j = idx / 112, i = idx % 112;
        sm[O_WM2 + i * 49 + j] = WM2[idx];
    }
    for (int idx = tid; idx < 2304; idx += 512) {       // WM3 [48][48] -> [i][j] s49
        int j = idx / 48, i = idx % 48;
        sm[O_WM3 + i * 49 + j] = WM3[idx];
    }
    for (int idx = tid; idx < 768; idx += 512) {        // WO1 [16][48] -> [i=48][j=16] s17
        int j = idx / 48, i = idx % 48;
        sm[O_WO1 + i * 17 + j] = WO1[idx];
    }
    if (tid < 48)  sm[O_B + tid]        = bI1[tid];
    if (tid < 16)  sm[O_B + 48 + tid]   = bA1[tid];
    if (tid < 48)  sm[O_B + 64 + tid]   = bM1[tid];
    if (tid < 48)  sm[O_B + 112 + tid]  = bM2[tid];
    if (tid < 48)  sm[O_B + 160 + tid]  = bM3[tid];
    if (tid < 48)  sm[O_B + 208 + tid]  = lng[tid];
    if (tid < 48)  sm[O_B + 256 + tid]  = lnb[tid];
    if (tid < 16)  sm[O_B + 304 + tid]  = bO1[tid];
    __syncthreads();

    const int lane = tid & 31;
    const int w    = tid >> 5;
    const int b    = blockIdx.x * 16 + w;
    float* ws = sm + O_WS + w * 192;   // out[0..47] op[48..63] h[64..111] tp/h2[112..159] sc[160..179]
    const float* sG  = sm + O_B + 208;
    const float* sBt = sm + O_B + 256;

    // row inputs (uniform per warp -> broadcast loads)
    float x[DIM], c[DIM];
    {
        const float4* xp = (const float4*)(we  + (size_t)b * DIM);
        const float4* cp = (const float4*)(ctx + (size_t)b * DIM);
#pragma unroll
        for (int q = 0; q < 4; q++) {
            float4 vx = __ldg(&xp[q]); x[q*4+0]=vx.x; x[q*4+1]=vx.y; x[q*4+2]=vx.z; x[q*4+3]=vx.w;
            float4 vc = __ldg(&cp[q]); c[q*4+0]=vc.x; c[q*4+1]=vc.y; c[q*4+2]=vc.z; c[q*4+3]=vc.w;
        }
    }

    // ---- I1: out[48] ----
    {
        float a = sm[O_B + lane];
        float a2 = (lane < 16) ? sm[O_B + 32 + lane] : 0.f;
#pragma unroll
        for (int i = 0; i < DIM; i++) {
            a += sm[O_WI1 + i * 49 + lane] * x[i];
            if (lane < 16) a2 += sm[O_WI1 + i * 49 + 32 + lane] * x[i];
        }
        ws[lane] = a;
        if (lane < 16) ws[32 + lane] = a2;
    }
    __syncwarp();

    // ---- A1: op[16] ----
    if (lane < 16) {
        float a = sm[O_B + 48 + lane];
#pragma unroll
        for (int i = 0; i < DIM1; i++) a += sm[O_WA1 + i * 17 + lane] * ws[i];
        ws[48 + lane] = a;
    }
    __syncwarp();

    // ---- M1 + LN + SiLU -> h[48] ----
    {
        float hA = sm[O_B + 64 + lane];
        float hB = (lane < 16) ? sm[O_B + 64 + 32 + lane] : 0.f;
#pragma unroll
        for (int i = 0; i < DIM1; i++) {
            float vi = ws[i];
            hA += sm[O_WM1 + i * 49 + lane] * vi;
            if (lane < 16) hB += sm[O_WM1 + i * 49 + 32 + lane] * vi;
        }
#pragma unroll
        for (int i = 0; i < DIM; i++) {
            hA += sm[O_WM1 + (48 + i) * 49 + lane] * c[i];
            if (lane < 16) hB += sm[O_WM1 + (48 + i) * 49 + 32 + lane] * c[i];
        }
#pragma unroll
        for (int i = 0; i < DIM; i++) {
            float vi = ws[48 + i];
            hA += sm[O_WM1 + (64 + i) * 49 + lane] * vi;
            if (lane < 16) hB += sm[O_WM1 + (64 + i) * 49 + 32 + lane] * vi;
        }
        ln_silu_warp(hA, hB, lane, sG, sBt);
        ws[64 + lane] = hA;
        if (lane < 16) ws[96 + lane] = hB;
    }
    __syncwarp();

    // ---- scores ----
    if (lane < TTH) {
        const float4* tr = (const float4*)(th + (size_t)b * TTH * DIM + lane * DIM);
        float s = 0.f;
#pragma unroll
        for (int q = 0; q < 4; q++) {
            float4 v = __ldg(&tr[q]);
            s += v.x * ws[48 + q*4+0] + v.y * ws[48 + q*4+1]
               + v.z * ws[48 + q*4+2] + v.w * ws[48 + q*4+3];
        }
        ws[160 + lane] = s;
    }
    __syncwarp();

    // ---- top-3 (replicated per lane; identical compare chain to reference) ----
    float s0 = -3.0e38f, s1 = -3.0e38f, s2 = -3.0e38f;
    int   i0 = 0, i1 = 0, i2 = 0;
#pragma unroll
    for (int t = 0; t < TTH; t++) {
        float s = ws[160 + t];
        if (s > s0)      { s2=s1; i2=i1; s1=s0; i1=i0; s0=s; i0=t; }
        else if (s > s1) { s2=s1; i2=i1; s1=s;  i1=t; }
        else if (s > s2) { s2=s;  i2=t; }
    }
    if (lane < 16) {
        const float* tb = th + (size_t)b * TTH * DIM;
        ws[112 + lane] = __ldg(&tb[i0 * DIM + lane]);
        ws[128 + lane] = __ldg(&tb[i1 * DIM + lane]);
        ws[144 + lane] = __ldg(&tb[i2 * DIM + lane]);
    }
    __syncwarp();

    // ---- M2 + LN + SiLU -> h2 ----
    float h2A, h2B;
    {
        float hA = sm[O_B + 112 + lane];
        float hB = (lane < 16) ? sm[O_B + 112 + 32 + lane] : 0.f;
#pragma unroll
        for (int i = 0; i < DIM1; i++) {
            float vi = ws[64 + i];
            hA += sm[O_WM2 + i * 49 + lane] * vi;
            if (lane < 16) hB += sm[O_WM2 + i * 49 + 32 + lane] * vi;
        }
#pragma unroll
        for (int i = 0; i < DIM1; i++) {
            float vi = ws[112 + i];
            hA += sm[O_WM2 + (48 + i) * 49 + lane] * vi;
            if (lane < 16) hB += sm[O_WM2 + (48 + i) * 49 + 32 + lane] * vi;
        }
#pragma unroll
        for (int i = 0; i < DIM; i++) {
            hA += sm[O_WM2 + (96 + i) * 49 + lane] * c[i];
            if (lane < 16) hB += sm[O_WM2 + (96 + i) * 49 + 32 + lane] * c[i];
        }
        ln_silu_warp(hA, hB, lane, sG, sBt);
        h2A = hA; h2B = hB;
    }
    __syncwarp();                 // everyone done reading ws[112..159] (tp)
    ws[112 + lane] = h2A;
    if (lane < 16) ws[144 + lane] = h2B;
    __syncwarp();

    // ---- M3 + LN + SiLU -> h3 ----
    float h3A, h3B;
    {
        float hA = sm[O_B + 160 + lane];
        float hB = (lane < 16) ? sm[O_B + 160 + 32 + lane] : 0.f;
#pragma unroll
        for (int i = 0; i < DIM1; i++) {
            float vi = ws[112 + i];
            hA += sm[O_WM3 + i * 49 + lane] * vi;
            if (lane < 16) hB += sm[O_WM3 + i * 49 + 32 + lane] * vi;
        }
        ln_silu_warp(hA, hB, lane, sG, sBt);
        h3A = hA; h3B = hB;
    }
    ws[lane] = h3A;               // slot 0..47 free (out no longer needed)
    if (lane < 16) ws[32 + lane] = h3B;
    __syncwarp();

    // ---- O1 -> g_o ----
    if (lane < 16) {
        float a = sm[O_B + 304 + lane];
#pragma unroll
        for (int i = 0; i < DIM1; i++) a += sm[O_WO1 + i * 17 + lane] * ws[i];
        g_o[(size_t)b * DIM + lane] = a;
    }
}

// ---------------------------------------------------------------------------
// Stage 2: logits GEMM  [8192,16] x [16,32000] -> [8192,32000]
// R8-proven version, verbatim: block tile 64b x 128v, 128 threads, 4 CTAs/SM,
// thread tile 8x8 FFMA2; E transpose folded into the contiguous tile load.
// ---------------------------------------------------------------------------
#define ES_STRIDE 132   // floats; bank-skewed rows

__global__ __launch_bounds__(128, 4) void k_gemm(const float* __restrict__ E,
                                                 float* __restrict__ out)
{
    __shared__ float es[DIM][ES_STRIDE];   // es[k][v]
    __shared__ float os[DIM][64];          // os[k][b]

    const int tid = threadIdx.x;
    const int v0 = blockIdx.x * 128;
    const int b0 = blockIdx.y * 64;

    // Load E tile rows v0..v0+127 (8 KB contiguous) and transpose into es.
    const float4* Eb = (const float4*)(E + (size_t)v0 * DIM);
#pragma unroll
    for (int q = 0; q < 4; q++) {
        int f = tid + q * 128;          // float4 index 0..511
        float4 v = Eb[f];
        int row = f >> 2;               // vocab row within tile
        int kc  = (f & 3) * 4;          // k-chunk
        es[kc + 0][row] = v.x;
        es[kc + 1][row] = v.y;
        es[kc + 2][row] = v.z;
        es[kc + 3][row] = v.w;
    }
    // Load o tile (plain floats, transposed)
    if (tid < 64) {
        const float4* orow = (const float4*)&g_o[(size_t)(b0 + tid) * DIM];
#pragma unroll
        for (int q = 0; q < 4; q++) {
            float4 r = orow[q];
            os[q * 4 + 0][tid] = r.x;
            os[q * 4 + 1][tid] = r.y;
            os[q * 4 + 2][tid] = r.z;
            os[q * 4 + 3][tid] = r.w;
        }
    }
    __syncthreads();

    const int tx = tid & 15;    // vocab: cols tx*4..+3 and 64+tx*4..+3
    const int ty = tid >> 4;    // batch: rows b0 + ty*8 .. +7

    unsigned long long acc[8][4];
#pragma unroll
    for (int m = 0; m < 8; m++)
#pragma unroll
        for (int n = 0; n < 4; n++) acc[m][n] = 0ull;

#pragma unroll
    for (int k = 0; k < DIM; k++) {
        ulonglong2 eA = *(const ulonglong2*)&es[k][tx * 4];        // LDS.128
        ulonglong2 eB = *(const ulonglong2*)&es[k][64 + tx * 4];   // LDS.128
        float4 oA = *(const float4*)&os[k][ty * 8];                // LDS.128 bcast
        float4 oB = *(const float4*)&os[k][ty * 8 + 4];            // LDS.128 bcast
        unsigned long long a0 = fdup(oA.x), a1 = fdup(oA.y);
        unsigned long long a2 = fdup(oA.z), a3 = fdup(oA.w);
        unsigned long long a4 = fdup(oB.x), a5 = fdup(oB.y);
        unsigned long long a6 = fdup(oB.z), a7 = fdup(oB.w);
        unsigned long long av[8] = {a0, a1, a2, a3, a4, a5, a6, a7};
#pragma unroll
        for (int m = 0; m < 8; m++) {
            acc[m][0] = f2fma(av[m], eA.x, acc[m][0]);
            acc[m][1] = f2fma(av[m], eA.y, acc[m][1]);
            acc[m][2] = f2fma(av[m], eB.x, acc[m][2]);
            acc[m][3] = f2fma(av[m], eB.y, acc[m][3]);
        }
    }

    union U { ulonglong2 u; float4 f; };
#pragma unroll
    for (int m = 0; m < 8; m++) {
        size_t row = (size_t)(b0 + ty * 8 + m) * VOCAB + v0;
        U u1; u1.u.x = acc[m][0]; u1.u.y = acc[m][1];
        U u2; u2.u.x = acc[m][2]; u2.u.y = acc[m][3];
        __stcs((float4*)&out[row + tx * 4],      u1.f);   // streaming store
        __stcs((float4*)&out[row + 64 + tx * 4], u2.f);
    }
}

// ---------------------------------------------------------------------------
extern "C" void kernel_launch(void* const* d_in, const int* in_sizes, int n_in,
                              void* d_out, int out_size) {
    const float* we  = (const float*)d_in[0];
    const float* ctx = (const float*)d_in[1];
    const float* th  = (const float*)d_in[2];
    const float* WI1 = (const float*)d_in[3];  const float* bI1 = (const float*)d_in[4];
    const float* WA1 = (const float*)d_in[5];  const float* bA1 = (const float*)d_in[6];
    const float* WM1 = (const float*)d_in[7];  const float* bM1 = (const float*)d_in[8];
    const float* WM2 = (const float*)d_in[9];  const float* bM2 = (const float*)d_in[10];
    const float* WM3 = (const float*)d_in[11]; const float* bM3 = (const float*)d_in[12];
    const float* lng = (const float*)d_in[13]; const float* lnb = (const float*)d_in[14];
    const float* WO1 = (const float*)d_in[15]; const float* bO1 = (const float*)d_in[16];
    const float* E   = (const float*)d_in[17];
    float* out = (float*)d_out;

    // Unconditional (no static guard): deterministic, idempotent, capture-safe.
    cudaFuncSetAttribute(k_stage1, cudaFuncAttributeMaxDynamicSharedMemorySize,
                         SM_FLOATS * 4);

    k_stage1<<<BATCH / 16, 512, SM_FLOATS * 4>>>(we, ctx, th, WI1, bI1, WA1, bA1,
                                                 WM1, bM1, WM2, bM2, WM3, bM3,
                                                 lng, lnb, WO1, bO1);
    dim3 grid(VOCAB / 128, BATCH / 64);
    k_gemm<<<grid, 128>>>(E, out);
}